// round 1
// baseline (speedup 1.0000x reference)
#include <cuda_runtime.h>

#define NN 4096
#define FF 256
#define EE 65536
#define ADJ_CAP 128
#define NBR_CAP 4096
#define ZW (NN/32)

// ---- device scratch (no allocations allowed) ----
__device__ float    g_A [(size_t)NN*NN];   // 64 MB
__device__ float    g_A2[(size_t)NN*NN];   // 64 MB
__device__ unsigned g_Z [(size_t)NN*ZW];   // 2 MB
__device__ int      g_adjcol[(size_t)NN*ADJ_CAP];
__device__ float    g_adjval[(size_t)NN*ADJ_CAP];
__device__ int      g_adjcnt[NN];
__device__ int      g_D[NN];
__device__ int      g_Dr[NN];
__device__ float    g_sq[NN];
__device__ float    g_dthres;

// ---- zero both dense matrices ----
__global__ void k_zero() {
    size_t total = (size_t)NN*NN;
    size_t stride = (size_t)gridDim.x * blockDim.x;
    for (size_t i = (size_t)blockIdx.x*blockDim.x + threadIdx.x; i < total; i += stride) {
        g_A[i]  = 0.f;
        g_A2[i] = 0.f;
    }
}

// ---- scatter-add edge weights ----
__global__ void k_scatter(const int* __restrict__ ei, const float* __restrict__ w) {
    int e = blockIdx.x*blockDim.x + threadIdx.x;
    if (e < EE) {
        int u = ei[e], v = ei[EE + e];
        atomicAdd(&g_A[(size_t)u*NN + v], w[e]);
    }
}

// ---- add identity, clamp >1 to 1 ----
__global__ void k_diag_clamp() {
    size_t i = (size_t)blockIdx.x*blockDim.x + threadIdx.x;
    if (i < (size_t)NN*NN) {
        int r = (int)(i >> 12);
        int c = (int)(i & (NN-1));
        float v = g_A[i];
        if (r == c) v += 1.f;
        g_A[i] = fminf(v, 1.f);
    }
}

// ---- per-row CSR-ish adjacency list of A (incl. diagonal), and D = nnz-1 ----
__global__ void k_build_adj() {
    int u = blockIdx.x;
    __shared__ int scnt;
    if (threadIdx.x == 0) scnt = 0;
    __syncthreads();
    const float* row = g_A + (size_t)u*NN;
    for (int j = threadIdx.x; j < NN; j += blockDim.x) {
        float v = row[j];
        if (v != 0.f) {
            int p = atomicAdd(&scnt, 1);
            if (p < ADJ_CAP) { g_adjcol[(size_t)u*ADJ_CAP+p] = j; g_adjval[(size_t)u*ADJ_CAP+p] = v; }
        }
    }
    __syncthreads();
    if (threadIdx.x == 0) {
        g_adjcnt[u] = min(scnt, ADJ_CAP);
        g_D[u] = scnt - 1;   // diagonal is always nonzero (==1)
    }
}

// ---- zero diagonal of A (after adj build; A2 diagonal never written) ----
__global__ void k_zero_diag() {
    int i = blockIdx.x*blockDim.x + threadIdx.x;
    if (i < NN) g_A[(size_t)i*NN + i] = 0.f;
}

// ---- sparse A@A per row into smem-dense accumulator; write off-diag nnz; Dr ----
__global__ void k_spgemm() {
    int u = blockIdx.x;
    __shared__ float acc[NN];            // 16 KB
    __shared__ int   ucol[ADJ_CAP];
    __shared__ float uval[ADJ_CAP];
    __shared__ int   sDr;
    for (int j = threadIdx.x; j < NN; j += blockDim.x) acc[j] = 0.f;
    int mu = g_adjcnt[u];
    for (int p = threadIdx.x; p < mu; p += blockDim.x) {
        ucol[p] = g_adjcol[(size_t)u*ADJ_CAP+p];
        uval[p] = g_adjval[(size_t)u*ADJ_CAP+p];
    }
    if (threadIdx.x == 0) sDr = 0;
    __syncthreads();
    int total = mu * ADJ_CAP;
    for (int p = threadIdx.x; p < total; p += blockDim.x) {
        int ki = p >> 7;                 // / ADJ_CAP
        int qi = p & (ADJ_CAP-1);
        int k  = ucol[ki];
        if (qi < g_adjcnt[k]) {
            int   j = g_adjcol[(size_t)k*ADJ_CAP+qi];
            float v = uval[ki] * g_adjval[(size_t)k*ADJ_CAP+qi];
            atomicAdd(&acc[j], v);
        }
    }
    __syncthreads();
    int dr = 0;
    float* outrow = g_A2 + (size_t)u*NN;
    for (int j = threadIdx.x; j < NN; j += blockDim.x) {
        float v = acc[j];
        if (v != 0.f && j != u) { outrow[j] = v; dr++; }
    }
    // reduce dr
    for (int o = 16; o > 0; o >>= 1) dr += __shfl_down_sync(0xffffffffu, dr, o);
    if ((threadIdx.x & 31) == 0) atomicAdd(&sDr, dr);
    __syncthreads();
    if (threadIdx.x == 0) g_Dr[u] = sDr;
}

// ---- d_thres = mean(D) + 2*std(D) ----
__global__ void k_stats() {
    __shared__ double s1[32], s2s[32];
    double s = 0.0, sq = 0.0;
    for (int i = threadIdx.x; i < NN; i += blockDim.x) {
        double d = (double)g_D[i];
        s += d; sq += d*d;
    }
    for (int o = 16; o > 0; o >>= 1) {
        s  += __shfl_down_sync(0xffffffffu, s,  o);
        sq += __shfl_down_sync(0xffffffffu, sq, o);
    }
    int lane = threadIdx.x & 31, wid = threadIdx.x >> 5;
    if (lane == 0) { s1[wid] = s; s2s[wid] = sq; }
    __syncthreads();
    if (threadIdx.x == 0) {
        double S = 0.0, SQ = 0.0;
        int nw = blockDim.x >> 5;
        for (int i = 0; i < nw; i++) { S += s1[i]; SQ += s2s[i]; }
        double mean = S / NN;
        double var  = SQ / NN - mean*mean;
        if (var < 0.0) var = 0.0;
        g_dthres = (float)(mean + 2.0 * sqrt(var));
    }
}

// ---- squared norms of feature rows ----
__global__ void k_sq(const float* __restrict__ X) {
    int u = blockIdx.x;
    float x = X[(size_t)u*FF + threadIdx.x];   // blockDim == FF == 256
    float v = x * x;
    __shared__ float red[8];
    for (int o = 16; o > 0; o >>= 1) v += __shfl_down_sync(0xffffffffu, v, o);
    if ((threadIdx.x & 31) == 0) red[threadIdx.x >> 5] = v;
    __syncthreads();
    if (threadIdx.x == 0) {
        float t = 0.f;
        for (int i = 0; i < 8; i++) t += red[i];
        g_sq[u] = t;
    }
}

// ---- build Z bitmask per row ----
__global__ void k_zbuild(const float* __restrict__ X) {
    int u   = blockIdx.x;
    int tid = threadIdx.x;
    int lane = tid & 31, wid = tid >> 5;

    __shared__ int      sidx [NBR_CAP];   // 16 KB
    __shared__ float    sdist[NBR_CAP];   // 16 KB
    __shared__ float    xu[FF];           // 1 KB
    __shared__ unsigned zw[ZW];           // 512 B
    __shared__ int      scnt;

    int   D  = g_D[u], Dr = g_Dr[u];
    float dthres = g_dthres;
    unsigned* Zrow       = g_Z  + (size_t)u*ZW;
    const float* A2row   = g_A2 + (size_t)u*NN;
    const float* Arow    = g_A  + (size_t)u*NN;

    bool highD = ((float)D > dthres);
    if (highD) {
        // Z = (A == 0) over the whole row (diag of A already zeroed -> bit set)
        for (int w32 = wid; w32 < ZW; w32 += 8) {
            int j = (w32 << 5) + lane;
            unsigned m = __ballot_sync(0xffffffffu, Arow[j] == 0.f);
            if (lane == 0) Zrow[w32] = m;
        }
        return;
    }
    if (2*D > Dr) {   // nosparse branch -> Z row all false
        for (int w = tid; w < ZW; w += blockDim.x) Zrow[w] = 0u;
        return;
    }
    int nz = Dr - 2*D;
    if (nz == 0) {
        // nz_eff = n -> all A2-neighbors selected
        for (int w32 = wid; w32 < ZW; w32 += 8) {
            int j = (w32 << 5) + lane;
            unsigned m = __ballot_sync(0xffffffffu, A2row[j] != 0.f);
            if (lane == 0) Zrow[w32] = m;
        }
        return;
    }

    // --- sparse branch: top-nz farthest A2-neighbors ---
    if (tid == 0) scnt = 0;
    xu[tid] = X[(size_t)u*FF + tid];
    __syncthreads();
    for (int j = tid; j < NN; j += blockDim.x) {
        if (A2row[j] != 0.f) {
            int p = atomicAdd(&scnt, 1);
            if (p < NBR_CAP) sidx[p] = j;
        }
    }
    __syncthreads();
    int m = min(scnt, NBR_CAP);

    // distances: one warp per neighbor (coalesced feature-row reads)
    float squ = g_sq[u];
    for (int nb = wid; nb < m; nb += 8) {
        int j = sidx[nb];
        const float* xj = X + (size_t)j*FF;
        float a = 0.f;
        for (int f = lane; f < FF; f += 32) a += xu[f] * xj[f];
        for (int o = 16; o > 0; o >>= 1) a += __shfl_down_sync(0xffffffffu, a, o);
        if (lane == 0) sdist[nb] = squ + g_sq[j] - 2.f * a;
    }
    __syncthreads();

    // pad to power of two
    int P = 1; while (P < m) P <<= 1;
    for (int i = m + tid; i < P; i += blockDim.x) { sdist[i] = -3.0e38f; sidx[i] = 0x7fffffff; }
    __syncthreads();

    // bitonic sort: desired order = dist DESC, tie by index ASC (stable-argsort match)
    for (int k2 = 2; k2 <= P; k2 <<= 1) {
        for (int j2 = k2 >> 1; j2 > 0; j2 >>= 1) {
            for (int i = tid; i < P; i += blockDim.x) {
                int ixj = i ^ j2;
                if (ixj > i) {
                    float di = sdist[i], dj = sdist[ixj];
                    int   ii = sidx[i],  ij = sidx[ixj];
                    bool pre = (di > dj) || (di == dj && ii < ij);
                    bool dir = ((i & k2) == 0);
                    if (dir ? !pre : pre) {
                        sdist[i] = dj; sdist[ixj] = di;
                        sidx[i]  = ij; sidx[ixj]  = ii;
                    }
                }
            }
            __syncthreads();
        }
    }

    // set bits for first nz (<= m) entries
    for (int w = tid; w < ZW; w += blockDim.x) zw[w] = 0u;
    __syncthreads();
    int sel = min(nz, m);
    for (int t = tid; t < sel; t += blockDim.x) {
        int j = sidx[t];
        atomicOr(&zw[j >> 5], 1u << (j & 31));
    }
    __syncthreads();
    for (int w = tid; w < ZW; w += blockDim.x) Zrow[w] = zw[w];
}

// ---- final per-edge output ----
__global__ void k_edge(const int* __restrict__ ei, const float* __restrict__ w,
                       const float* __restrict__ t1, const float* __restrict__ t2,
                       float* __restrict__ out) {
    int e = blockIdx.x*blockDim.x + threadIdx.x;
    if (e >= EE) return;
    int u = ei[e], v = ei[EE + e];
    float a  = g_A [(size_t)u*NN + v];
    float a2 = g_A2[(size_t)u*NN + v];
    unsigned zword = g_Z[(size_t)u*ZW + (v >> 5)];
    bool z = (zword >> (v & 31)) & 1u;
    float adj = z ? 0.f : (a2 - a);
    float val = t1[0]*w[e] + t2[0]*adj;
    out[e] = fmaxf(val, 0.f);
}

extern "C" void kernel_launch(void* const* d_in, const int* in_sizes, int n_in,
                              void* d_out, int out_size) {
    const int*   ei = (const int*)  d_in[0];   // (2, E) int32
    const float* w  = (const float*)d_in[1];   // (E,)
    const float* X  = (const float*)d_in[2];   // (N, F)
    const float* t1 = (const float*)d_in[3];   // (1,)
    const float* t2 = (const float*)d_in[4];   // (1,)
    float* out = (float*)d_out;                // (E,)

    k_zero      <<<4096, 256>>>();
    k_scatter   <<<EE/256, 256>>>(ei, w);
    k_diag_clamp<<<(int)(((size_t)NN*NN)/256), 256>>>();
    k_build_adj <<<NN, 256>>>();
    k_zero_diag <<<NN/256, 256>>>();
    k_spgemm    <<<NN, 256>>>();
    k_stats     <<<1, 256>>>();
    k_sq        <<<NN, 256>>>(X);
    k_zbuild    <<<NN, 256>>>(X);
    k_edge      <<<EE/256, 256>>>(ei, w, t1, t2, out);
}

// round 2
// speedup vs baseline: 1.4460x; 1.4460x over previous
#include <cuda_runtime.h>

#define NN 4096
#define FF 256
#define EE 65536
#define ADJ_CAP 128
#define NBR_CAP 2048
#define ZW (NN/32)

// ---- device scratch ----
__device__ float    g_A [(size_t)NN*NN];          // 64 MB (scatter-dedup only)
__device__ unsigned g_Z [(size_t)NN*ZW];          // 2 MB
__device__ int      g_adjcol[(size_t)NN*ADJ_CAP]; // sorted 1-hop cols (incl diag)
__device__ float    g_adjval[(size_t)NN*ADJ_CAP];
__device__ int      g_adjcnt[NN];
__device__ int      g_nbr [(size_t)NN*NBR_CAP];   // sorted 2-hop cols (excl diag)
__device__ float    g_nval[(size_t)NN*NBR_CAP];
__device__ int      g_D[NN];
__device__ int      g_Dr[NN];
__device__ float    g_sq[NN];
__device__ float    g_dthres;

// ---- zero dense A (float4) ----
__global__ void k_zero() {
    float4* p = (float4*)g_A;
    size_t total = (size_t)NN*NN/4;
    size_t stride = (size_t)gridDim.x * blockDim.x;
    float4 z = make_float4(0.f,0.f,0.f,0.f);
    for (size_t i = (size_t)blockIdx.x*blockDim.x + threadIdx.x; i < total; i += stride)
        p[i] = z;
}

// ---- scatter-add edge weights ----
__global__ void k_scatter(const int* __restrict__ ei, const float* __restrict__ w) {
    int e = blockIdx.x*blockDim.x + threadIdx.x;
    if (e < EE) {
        int u = ei[e], v = ei[EE + e];
        atomicAdd(&g_A[(size_t)u*NN + v], w[e]);
    }
}

// ---- build sorted adjacency list with fused (+I, clamp) ----
__global__ void k_build_adj() {
    int u   = blockIdx.x;
    int tid = threadIdx.x;
    int lane = tid & 31, wid = tid >> 5;

    __shared__ float rowbuf[NN];       // 16 KB transformed row
    __shared__ int   chunkcnt[128];
    __shared__ int   chunkoff[128];
    __shared__ int   stot;

    // stage + transform row (float4 reads, 4 per thread -> good MLP)
    const float4* rp = (const float4*)(g_A + (size_t)u*NN);
    #pragma unroll
    for (int it = 0; it < 4; it++) {
        int i4 = tid + it*256;              // float4 index 0..1023
        float4 v = rp[i4];
        int c0 = i4*4;
        v.x = (c0+0 == u) ? 1.f : fminf(v.x, 1.f);
        v.y = (c0+1 == u) ? 1.f : fminf(v.y, 1.f);
        v.z = (c0+2 == u) ? 1.f : fminf(v.z, 1.f);
        v.w = (c0+3 == u) ? 1.f : fminf(v.w, 1.f);
        *(float4*)&rowbuf[c0] = v;
    }
    __syncthreads();

    // per-chunk nonzero counts (warp w handles chunks w, w+8, ...)
    for (int c = wid; c < 128; c += 8) {
        float v = rowbuf[c*32 + lane];
        unsigned m = __ballot_sync(0xffffffffu, v != 0.f);
        if (lane == 0) chunkcnt[c] = __popc(m);
    }
    __syncthreads();
    if (tid == 0) {
        int run = 0;
        for (int c = 0; c < 128; c++) { chunkoff[c] = run; run += chunkcnt[c]; }
        stot = run;
        g_adjcnt[u] = min(run, ADJ_CAP);
        g_D[u] = run - 1;                  // diag always present
    }
    __syncthreads();

    // ordered compacted write
    for (int c = wid; c < 128; c += 8) {
        float v = rowbuf[c*32 + lane];
        unsigned m = __ballot_sync(0xffffffffu, v != 0.f);
        if (v != 0.f) {
            int pos = chunkoff[c] + __popc(m & ((1u << lane) - 1u));
            if (pos < ADJ_CAP) {
                g_adjcol[(size_t)u*ADJ_CAP + pos] = c*32 + lane;
                g_adjval[(size_t)u*ADJ_CAP + pos] = v;
            }
        }
    }
    (void)stot;
}

// ---- sparse A@A -> sorted per-row (col,val) list, Dr ----
__global__ void k_spgemm() {
    int u   = blockIdx.x;
    int tid = threadIdx.x;
    int lane = tid & 31, wid = tid >> 5;

    __shared__ float acc[NN];            // 16 KB
    __shared__ int   ucol[ADJ_CAP];
    __shared__ float uval[ADJ_CAP];
    __shared__ int   ucnt[ADJ_CAP];
    __shared__ int   chunkcnt[128];
    __shared__ int   chunkoff[128];

    #pragma unroll
    for (int it = 0; it < 16; it++) acc[tid + it*256] = 0.f;
    int mu = g_adjcnt[u];
    for (int p = tid; p < mu; p += 256) {
        int c = g_adjcol[(size_t)u*ADJ_CAP+p];
        ucol[p] = c;
        uval[p] = g_adjval[(size_t)u*ADJ_CAP+p];
        ucnt[p] = g_adjcnt[c];
    }
    __syncthreads();

    int total = mu * ADJ_CAP;
    for (int p = tid; p < total; p += 256) {
        int ki = p >> 7;
        int qi = p & (ADJ_CAP-1);
        if (qi < ucnt[ki]) {
            int   k = ucol[ki];
            int   j = g_adjcol[(size_t)k*ADJ_CAP+qi];
            float v = uval[ki] * g_adjval[(size_t)k*ADJ_CAP+qi];
            atomicAdd(&acc[j], v);
        }
    }
    __syncthreads();
    if (tid == 0) acc[u] = 0.f;          // setdiag(0)
    __syncthreads();

    for (int c = wid; c < 128; c += 8) {
        float v = acc[c*32 + lane];
        unsigned m = __ballot_sync(0xffffffffu, v != 0.f);
        if (lane == 0) chunkcnt[c] = __popc(m);
    }
    __syncthreads();
    if (tid == 0) {
        int run = 0;
        for (int c = 0; c < 128; c++) { chunkoff[c] = run; run += chunkcnt[c]; }
        g_Dr[u] = run;
    }
    __syncthreads();
    for (int c = wid; c < 128; c += 8) {
        float v = acc[c*32 + lane];
        unsigned m = __ballot_sync(0xffffffffu, v != 0.f);
        if (v != 0.f) {
            int pos = chunkoff[c] + __popc(m & ((1u << lane) - 1u));
            if (pos < NBR_CAP) {
                g_nbr [(size_t)u*NBR_CAP + pos] = c*32 + lane;
                g_nval[(size_t)u*NBR_CAP + pos] = v;
            }
        }
    }
}

// ---- d_thres = mean(D) + 2*std(D) ----
__global__ void k_stats() {
    __shared__ double s1[8], s2s[8];
    double s = 0.0, sq = 0.0;
    for (int i = threadIdx.x; i < NN; i += blockDim.x) {
        double d = (double)g_D[i];
        s += d; sq += d*d;
    }
    for (int o = 16; o > 0; o >>= 1) {
        s  += __shfl_down_sync(0xffffffffu, s,  o);
        sq += __shfl_down_sync(0xffffffffu, sq, o);
    }
    int lane = threadIdx.x & 31, wid = threadIdx.x >> 5;
    if (lane == 0) { s1[wid] = s; s2s[wid] = sq; }
    __syncthreads();
    if (threadIdx.x == 0) {
        double S = 0.0, SQ = 0.0;
        for (int i = 0; i < 8; i++) { S += s1[i]; SQ += s2s[i]; }
        double mean = S / NN;
        double var  = SQ / NN - mean*mean;
        if (var < 0.0) var = 0.0;
        g_dthres = (float)(mean + 2.0 * sqrt(var));
    }
}

// ---- squared norms ----
__global__ void k_sq(const float* __restrict__ X) {
    int u = blockIdx.x;
    float x = X[(size_t)u*FF + threadIdx.x];   // blockDim == 256
    float v = x * x;
    __shared__ float red[8];
    for (int o = 16; o > 0; o >>= 1) v += __shfl_down_sync(0xffffffffu, v, o);
    if ((threadIdx.x & 31) == 0) red[threadIdx.x >> 5] = v;
    __syncthreads();
    if (threadIdx.x == 0) {
        float t = 0.f;
        for (int i = 0; i < 8; i++) t += red[i];
        g_sq[u] = t;
    }
}

// ---- build Z bitmask per row ----
__global__ void k_zbuild(const float* __restrict__ X) {
    int u   = blockIdx.x;
    int tid = threadIdx.x;
    int lane = tid & 31, wid = tid >> 5;

    __shared__ int      scol [NBR_CAP];   // 8 KB
    __shared__ float    sdist[NBR_CAP];   // 8 KB
    __shared__ float    xu[FF];           // 1 KB
    __shared__ unsigned zw[ZW];           // 512 B

    int   D  = g_D[u], Dr = g_Dr[u];
    float dthres = g_dthres;
    unsigned* Zrow = g_Z + (size_t)u*ZW;

    bool highD = ((float)D > dthres);
    if (highD) {
        // Z = (A == 0); diag of A zeroed -> diag bit stays set
        for (int w = tid; w < ZW; w += 256) zw[w] = 0xffffffffu;
        __syncthreads();
        int cnt = g_adjcnt[u];
        for (int p = tid; p < cnt; p += 256) {
            int c = g_adjcol[(size_t)u*ADJ_CAP + p];
            if (c != u) atomicAnd(&zw[c >> 5], ~(1u << (c & 31)));
        }
        __syncthreads();
        for (int w = tid; w < ZW; w += 256) Zrow[w] = zw[w];
        return;
    }
    if (2*D > Dr) {   // nosparse -> all false
        for (int w = tid; w < ZW; w += 256) Zrow[w] = 0u;
        return;
    }
    int m = min(Dr, NBR_CAP);
    int nz = Dr - 2*D;
    if (nz == 0) {
        // nz_eff = n -> all A2-neighbors selected
        for (int w = tid; w < ZW; w += 256) zw[w] = 0u;
        __syncthreads();
        for (int p = tid; p < m; p += 256) {
            int c = g_nbr[(size_t)u*NBR_CAP + p];
            atomicOr(&zw[c >> 5], 1u << (c & 31));
        }
        __syncthreads();
        for (int w = tid; w < ZW; w += 256) Zrow[w] = zw[w];
        return;
    }

    // --- sparse branch: top-nz farthest A2-neighbors ---
    xu[tid] = X[(size_t)u*FF + tid];
    for (int p = tid; p < m; p += 256) scol[p] = g_nbr[(size_t)u*NBR_CAP + p];
    for (int w = tid; w < ZW; w += 256) zw[w] = 0u;
    __syncthreads();

    // preload xu fragments into registers (float4 per lane)
    float4 ax0 = *(const float4*)&xu[lane*4];
    float4 ax1 = *(const float4*)&xu[128 + lane*4];
    float squ = g_sq[u];

    for (int nb = wid; nb < m; nb += 8) {
        int j = scol[nb];
        const float4* xj = (const float4*)(X + (size_t)j*FF);
        float4 b0 = xj[lane];
        float4 b1 = xj[lane + 32];
        float a = ax0.x*b0.x + ax0.y*b0.y + ax0.z*b0.z + ax0.w*b0.w
                + ax1.x*b1.x + ax1.y*b1.y + ax1.z*b1.z + ax1.w*b1.w;
        for (int o = 16; o > 0; o >>= 1) a += __shfl_down_sync(0xffffffffu, a, o);
        if (lane == 0) sdist[nb] = squ + g_sq[j] - 2.f * a;
    }
    __syncthreads();

    // rank-count select: rank = #{j : d_j > d_i  or  (d_j == d_i and col_j < col_i)}
    // list is sorted by col, so list index order == col order.
    for (int i = tid; i < m; i += 256) {
        float di = sdist[i];
        int rank = 0;
        for (int j = 0; j < m; j++) {
            float dj = sdist[j];
            rank += (dj > di) || (dj == di && j < i);
        }
        if (rank < nz) {
            int c = scol[i];
            atomicOr(&zw[c >> 5], 1u << (c & 31));
        }
    }
    __syncthreads();
    for (int w = tid; w < ZW; w += 256) Zrow[w] = zw[w];
}

// ---- binary search in sorted col list ----
__device__ __forceinline__ int bsearch_col(const int* __restrict__ cols, int n, int v) {
    int lo = 0, hi = n;
    while (lo < hi) {
        int mid = (lo + hi) >> 1;
        if (cols[mid] < v) lo = mid + 1; else hi = mid;
    }
    return (lo < n && cols[lo] == v) ? lo : -1;
}

// ---- final per-edge output ----
__global__ void k_edge(const int* __restrict__ ei, const float* __restrict__ w,
                       const float* __restrict__ t1, const float* __restrict__ t2,
                       float* __restrict__ out) {
    int e = blockIdx.x*blockDim.x + threadIdx.x;
    if (e >= EE) return;
    int u = ei[e], v = ei[EE + e];
    float a = 0.f, a2 = 0.f;
    if (v != u) {
        int c = g_adjcnt[u];
        int p = bsearch_col(g_adjcol + (size_t)u*ADJ_CAP, c, v);
        if (p >= 0) a = g_adjval[(size_t)u*ADJ_CAP + p];
        int m = min(g_Dr[u], NBR_CAP);
        int q = bsearch_col(g_nbr + (size_t)u*NBR_CAP, m, v);
        if (q >= 0) a2 = g_nval[(size_t)u*NBR_CAP + q];
    }
    unsigned zword = g_Z[(size_t)u*ZW + (v >> 5)];
    bool z = (zword >> (v & 31)) & 1u;
    float adj = z ? 0.f : (a2 - a);
    float val = t1[0]*w[e] + t2[0]*adj;
    out[e] = fmaxf(val, 0.f);
}

extern "C" void kernel_launch(void* const* d_in, const int* in_sizes, int n_in,
                              void* d_out, int out_size) {
    const int*   ei = (const int*)  d_in[0];
    const float* w  = (const float*)d_in[1];
    const float* X  = (const float*)d_in[2];
    const float* t1 = (const float*)d_in[3];
    const float* t2 = (const float*)d_in[4];
    float* out = (float*)d_out;

    k_zero     <<<2048, 256>>>();
    k_scatter  <<<EE/256, 256>>>(ei, w);
    k_build_adj<<<NN, 256>>>();
    k_spgemm   <<<NN, 256>>>();
    k_stats    <<<1, 256>>>();
    k_sq       <<<NN, 256>>>(X);
    k_zbuild   <<<NN, 256>>>(X);
    k_edge     <<<EE/256, 256>>>(ei, w, t1, t2, out);
}

// round 3
// speedup vs baseline: 1.7497x; 1.2101x over previous
#include <cuda_runtime.h>

#define NN 4096
#define FF 256
#define EE 65536
#define ADJ_CAP 128
#define NBR_CAP 2048
#define ZW (NN/32)

// ---- device scratch ----
__device__ unsigned g_Z [(size_t)NN*ZW];          // 2 MB
__device__ int      g_adjcol[(size_t)NN*ADJ_CAP]; // sorted 1-hop cols (incl diag)
__device__ float    g_adjval[(size_t)NN*ADJ_CAP];
__device__ int      g_adjcnt[NN];
__device__ int      g_nbr [(size_t)NN*NBR_CAP];   // sorted 2-hop cols (excl diag)
__device__ float    g_nval[(size_t)NN*NBR_CAP];
__device__ int      g_D[NN];
__device__ int      g_Dr[NN];
__device__ float    g_sq[NN];
__device__ float    g_dthres;
// edge bucketing
__device__ int      g_ecnt[NN];
__device__ int      g_eoff[NN+1];
__device__ int      g_ecur[NN];
__device__ int      g_ev[EE];
__device__ float    g_ew[EE];

// ---- zero per-row edge counters ----
__global__ void k_zero_cnt() {
    int i = blockIdx.x*blockDim.x + threadIdx.x;
    if (i < NN) g_ecnt[i] = 0;
}

// ---- histogram edges by source ----
__global__ void k_hist(const int* __restrict__ ei) {
    int e = blockIdx.x*blockDim.x + threadIdx.x;
    if (e < EE) atomicAdd(&g_ecnt[ei[e]], 1);
}

// ---- exclusive scan of 4096 counts (1 block, 1024 threads, 4/thread) ----
__global__ void k_escan() {
    __shared__ int warpsum[32];
    int tid = threadIdx.x;
    int lane = tid & 31, wid = tid >> 5;
    int c0 = g_ecnt[tid*4+0], c1 = g_ecnt[tid*4+1],
        c2 = g_ecnt[tid*4+2], c3 = g_ecnt[tid*4+3];
    int s = c0 + c1 + c2 + c3;
    int v = s;
    #pragma unroll
    for (int o = 1; o < 32; o <<= 1) {
        int t = __shfl_up_sync(0xffffffffu, v, o);
        if (lane >= o) v += t;
    }
    if (lane == 31) warpsum[wid] = v;
    __syncthreads();
    if (wid == 0) {
        int w = warpsum[lane];
        #pragma unroll
        for (int o = 1; o < 32; o <<= 1) {
            int t = __shfl_up_sync(0xffffffffu, w, o);
            if (lane >= o) w += t;
        }
        warpsum[lane] = w;
    }
    __syncthreads();
    int base = (wid > 0 ? warpsum[wid-1] : 0) + (v - s);
    int run = base;
    g_eoff[tid*4+0] = run; g_ecur[tid*4+0] = run; run += c0;
    g_eoff[tid*4+1] = run; g_ecur[tid*4+1] = run; run += c1;
    g_eoff[tid*4+2] = run; g_ecur[tid*4+2] = run; run += c2;
    g_eoff[tid*4+3] = run; g_ecur[tid*4+3] = run; run += c3;
    if (tid == 1023) g_eoff[NN] = run;
}

// ---- bucket edges by source row ----
__global__ void k_ebucket(const int* __restrict__ ei, const float* __restrict__ w) {
    int e = blockIdx.x*blockDim.x + threadIdx.x;
    if (e < EE) {
        int u = ei[e];
        int p = atomicAdd(&g_ecur[u], 1);
        g_ev[p] = ei[EE + e];
        g_ew[p] = w[e];
    }
}

// 128-word warp scan helper result: woff (exclusive), returns total via woff[128]
__device__ __forceinline__ void mask_scan_warp0(const unsigned* mask, int* woff,
                                                int tid, int lane, int wid) {
    if (wid == 0) {
        int c0 = __popc(mask[lane*4+0]);
        int c1 = __popc(mask[lane*4+1]);
        int c2 = __popc(mask[lane*4+2]);
        int c3 = __popc(mask[lane*4+3]);
        int s = c0+c1+c2+c3;
        int v = s;
        #pragma unroll
        for (int o = 1; o < 32; o <<= 1) {
            int t = __shfl_up_sync(0xffffffffu, v, o);
            if (lane >= o) v += t;
        }
        int run = v - s;
        woff[lane*4+0] = run; run += c0;
        woff[lane*4+1] = run; run += c1;
        woff[lane*4+2] = run; run += c2;
        woff[lane*4+3] = run; run += c3;
        if (lane == 31) woff[128] = run;   // total
    }
}

// ---- build sorted adjacency (fused scatter-dedup, +I, clamp) ----
__global__ void k_build_adj() {
    int u   = blockIdx.x;
    int tid = threadIdx.x;
    int lane = tid & 31, wid = tid >> 5;

    __shared__ float    srow[NN];       // 16 KB
    __shared__ unsigned mask[128];
    __shared__ int      woff[129];

    float4* s4 = (float4*)srow;
    float4 z = make_float4(0.f,0.f,0.f,0.f);
    #pragma unroll
    for (int it = 0; it < 4; it++) s4[tid + it*256] = z;
    if (tid < 128) mask[tid] = 0u;
    __syncthreads();

    int eb = g_eoff[u], ee = g_eoff[u+1];
    for (int p = eb + tid; p < ee; p += 256) {
        int v = g_ev[p];
        atomicAdd(&srow[v], g_ew[p]);
        atomicOr(&mask[v >> 5], 1u << (v & 31));
    }
    __syncthreads();
    if (tid == 0) {
        srow[u] += 1.f;                  // + I
        atomicOr(&mask[u >> 5], 1u << (u & 31));
    }
    __syncthreads();

    mask_scan_warp0(mask, woff, tid, lane, wid);
    __syncthreads();
    int tot = woff[128];
    if (tid == 0) {
        g_adjcnt[u] = min(tot, ADJ_CAP);
        g_D[u] = tot - 1;
    }
    for (int slot = tid; slot < NN; slot += 256) {
        int w32 = slot >> 5, b = slot & 31;
        unsigned mw = mask[w32];
        if ((mw >> b) & 1u) {
            int pos = woff[w32] + __popc(mw & ((1u << b) - 1u));
            if (pos < ADJ_CAP) {
                g_adjcol[(size_t)u*ADJ_CAP + pos] = slot;
                g_adjval[(size_t)u*ADJ_CAP + pos] = fminf(srow[slot], 1.f); // clamp
            }
        }
    }
}

// ---- sparse A@A -> sorted per-row (col,val), Dr ----
__global__ void k_spgemm() {
    int u   = blockIdx.x;
    int tid = threadIdx.x;
    int lane = tid & 31, wid = tid >> 5;

    __shared__ float    acc[NN];        // 16 KB
    __shared__ unsigned mask[128];
    __shared__ int      woff[129];
    __shared__ int      ucol[ADJ_CAP];
    __shared__ float    uval[ADJ_CAP];
    __shared__ int      poff[ADJ_CAP+1];
    __shared__ int      smu, stot;

    float4* a4 = (float4*)acc;
    float4 z = make_float4(0.f,0.f,0.f,0.f);
    #pragma unroll
    for (int it = 0; it < 4; it++) a4[tid + it*256] = z;
    if (tid < 128) mask[tid] = 0u;
    if (tid == 0) smu = g_adjcnt[u];
    __syncthreads();
    int mu = smu;
    for (int p = tid; p < mu; p += 256) {
        int c = g_adjcol[(size_t)u*ADJ_CAP+p];
        ucol[p] = c;
        uval[p] = g_adjval[(size_t)u*ADJ_CAP+p];
        poff[p] = g_adjcnt[c];           // temp: counts
    }
    __syncthreads();
    if (tid == 0) {                      // serial scan over ~17 entries
        int run = 0;
        for (int k = 0; k < mu; k++) { int c = poff[k]; poff[k] = run; run += c; }
        poff[mu] = run;
        stot = run;
    }
    __syncthreads();
    int totprod = stot;

    for (int p = tid; p < totprod; p += 256) {
        // binary search: largest ki with poff[ki] <= p
        int lo = 0, hi = mu - 1;
        while (lo < hi) {
            int mid = (lo + hi + 1) >> 1;
            if (poff[mid] <= p) lo = mid; else hi = mid - 1;
        }
        int ki = lo;
        int qi = p - poff[ki];
        int k  = ucol[ki];
        int   j = g_adjcol[(size_t)k*ADJ_CAP+qi];
        float v = uval[ki] * g_adjval[(size_t)k*ADJ_CAP+qi];
        atomicAdd(&acc[j], v);
        atomicOr(&mask[j >> 5], 1u << (j & 31));
    }
    __syncthreads();
    if (tid == 0) mask[u >> 5] &= ~(1u << (u & 31));   // setdiag(0)
    __syncthreads();

    mask_scan_warp0(mask, woff, tid, lane, wid);
    __syncthreads();
    int tot = woff[128];
    if (tid == 0) g_Dr[u] = tot;
    for (int slot = tid; slot < NN; slot += 256) {
        int w32 = slot >> 5, b = slot & 31;
        unsigned mw = mask[w32];
        if ((mw >> b) & 1u) {
            int pos = woff[w32] + __popc(mw & ((1u << b) - 1u));
            if (pos < NBR_CAP) {
                g_nbr [(size_t)u*NBR_CAP + pos] = slot;
                g_nval[(size_t)u*NBR_CAP + pos] = acc[slot];
            }
        }
    }
}

// ---- d_thres = mean(D) + 2*std(D) ----
__global__ void k_stats() {
    __shared__ double s1[8], s2s[8];
    double s = 0.0, sq = 0.0;
    for (int i = threadIdx.x; i < NN; i += blockDim.x) {
        double d = (double)g_D[i];
        s += d; sq += d*d;
    }
    for (int o = 16; o > 0; o >>= 1) {
        s  += __shfl_down_sync(0xffffffffu, s,  o);
        sq += __shfl_down_sync(0xffffffffu, sq, o);
    }
    int lane = threadIdx.x & 31, wid = threadIdx.x >> 5;
    if (lane == 0) { s1[wid] = s; s2s[wid] = sq; }
    __syncthreads();
    if (threadIdx.x == 0) {
        double S = 0.0, SQ = 0.0;
        for (int i = 0; i < 8; i++) { S += s1[i]; SQ += s2s[i]; }
        double mean = S / NN;
        double var  = SQ / NN - mean*mean;
        if (var < 0.0) var = 0.0;
        g_dthres = (float)(mean + 2.0 * sqrt(var));
    }
}

// ---- squared norms ----
__global__ void k_sq(const float* __restrict__ X) {
    int u = blockIdx.x;
    float x = X[(size_t)u*FF + threadIdx.x];
    float v = x * x;
    __shared__ float red[8];
    for (int o = 16; o > 0; o >>= 1) v += __shfl_down_sync(0xffffffffu, v, o);
    if ((threadIdx.x & 31) == 0) red[threadIdx.x >> 5] = v;
    __syncthreads();
    if (threadIdx.x == 0) {
        float t = 0.f;
        for (int i = 0; i < 8; i++) t += red[i];
        g_sq[u] = t;
    }
}

// ---- build Z bitmask per row ----
__global__ void k_zbuild(const float* __restrict__ X) {
    int u   = blockIdx.x;
    int tid = threadIdx.x;
    int lane = tid & 31, wid = tid >> 5;

    __shared__ int      scol [NBR_CAP];
    __shared__ float    sdist[NBR_CAP];
    __shared__ float    xu[FF];
    __shared__ unsigned zw[ZW];

    int   D  = g_D[u], Dr = g_Dr[u];
    float dthres = g_dthres;
    unsigned* Zrow = g_Z + (size_t)u*ZW;

    bool highD = ((float)D > dthres);
    if (highD) {
        for (int w = tid; w < ZW; w += 256) zw[w] = 0xffffffffu;
        __syncthreads();
        int cnt = g_adjcnt[u];
        for (int p = tid; p < cnt; p += 256) {
            int c = g_adjcol[(size_t)u*ADJ_CAP + p];
            if (c != u) atomicAnd(&zw[c >> 5], ~(1u << (c & 31)));
        }
        __syncthreads();
        for (int w = tid; w < ZW; w += 256) Zrow[w] = zw[w];
        return;
    }
    if (2*D > Dr) {
        for (int w = tid; w < ZW; w += 256) Zrow[w] = 0u;
        return;
    }
    int m = min(Dr, NBR_CAP);
    int nz = Dr - 2*D;
    if (nz == 0) {
        for (int w = tid; w < ZW; w += 256) zw[w] = 0u;
        __syncthreads();
        for (int p = tid; p < m; p += 256) {
            int c = g_nbr[(size_t)u*NBR_CAP + p];
            atomicOr(&zw[c >> 5], 1u << (c & 31));
        }
        __syncthreads();
        for (int w = tid; w < ZW; w += 256) Zrow[w] = zw[w];
        return;
    }

    // --- sparse branch ---
    xu[tid] = X[(size_t)u*FF + tid];
    for (int p = tid; p < m; p += 256) scol[p] = g_nbr[(size_t)u*NBR_CAP + p];
    for (int w = tid; w < ZW; w += 256) zw[w] = 0u;
    __syncthreads();

    float4 ax0 = *(const float4*)&xu[lane*4];
    float4 ax1 = *(const float4*)&xu[128 + lane*4];
    float squ = g_sq[u];

    // two neighbors per warp iteration -> 4 outstanding 128B loads per lane
    for (int nb = wid*2; nb < m; nb += 16) {
        int j0 = scol[nb];
        int j1 = (nb+1 < m) ? scol[nb+1] : j0;
        const float4* xa = (const float4*)(X + (size_t)j0*FF);
        const float4* xb = (const float4*)(X + (size_t)j1*FF);
        float4 a0 = xa[lane],      b0 = xb[lane];
        float4 a1 = xa[lane + 32], b1 = xb[lane + 32];
        float da = a0.x*ax0.x + a0.y*ax0.y + a0.z*ax0.z + a0.w*ax0.w
                 + a1.x*ax1.x + a1.y*ax1.y + a1.z*ax1.z + a1.w*ax1.w;
        float db = b0.x*ax0.x + b0.y*ax0.y + b0.z*ax0.z + b0.w*ax0.w
                 + b1.x*ax1.x + b1.y*ax1.y + b1.z*ax1.z + b1.w*ax1.w;
        #pragma unroll
        for (int o = 16; o > 0; o >>= 1) {
            da += __shfl_down_sync(0xffffffffu, da, o);
            db += __shfl_down_sync(0xffffffffu, db, o);
        }
        if (lane == 0) {
            sdist[nb] = squ + g_sq[j0] - 2.f * da;
            if (nb+1 < m) sdist[nb+1] = squ + g_sq[j1] - 2.f * db;
        }
    }
    __syncthreads();

    // rank-count select (list sorted by col -> index order == col order)
    for (int i = tid; i < m; i += 256) {
        float di = sdist[i];
        int rank = 0;
        for (int j = 0; j < m; j++) {
            float dj = sdist[j];
            rank += (dj > di) || (dj == di && j < i);
        }
        if (rank < nz) {
            int c = scol[i];
            atomicOr(&zw[c >> 5], 1u << (c & 31));
        }
    }
    __syncthreads();
    for (int w = tid; w < ZW; w += 256) Zrow[w] = zw[w];
}

// ---- binary search in sorted col list ----
__device__ __forceinline__ int bsearch_col(const int* __restrict__ cols, int n, int v) {
    int lo = 0, hi = n;
    while (lo < hi) {
        int mid = (lo + hi) >> 1;
        if (cols[mid] < v) lo = mid + 1; else hi = mid;
    }
    return (lo < n && cols[lo] == v) ? lo : -1;
}

// ---- final per-edge output ----
__global__ void k_edge(const int* __restrict__ ei, const float* __restrict__ w,
                       const float* __restrict__ t1, const float* __restrict__ t2,
                       float* __restrict__ out) {
    int e = blockIdx.x*blockDim.x + threadIdx.x;
    if (e >= EE) return;
    int u = ei[e], v = ei[EE + e];
    float a = 0.f, a2 = 0.f;
    if (v != u) {
        int c = g_adjcnt[u];
        int p = bsearch_col(g_adjcol + (size_t)u*ADJ_CAP, c, v);
        if (p >= 0) a = g_adjval[(size_t)u*ADJ_CAP + p];
        int m = min(g_Dr[u], NBR_CAP);
        int q = bsearch_col(g_nbr + (size_t)u*NBR_CAP, m, v);
        if (q >= 0) a2 = g_nval[(size_t)u*NBR_CAP + q];
    }
    unsigned zword = g_Z[(size_t)u*ZW + (v >> 5)];
    bool z = (zword >> (v & 31)) & 1u;
    float adj = z ? 0.f : (a2 - a);
    float val = t1[0]*w[e] + t2[0]*adj;
    out[e] = fmaxf(val, 0.f);
}

extern "C" void kernel_launch(void* const* d_in, const int* in_sizes, int n_in,
                              void* d_out, int out_size) {
    const int*   ei = (const int*)  d_in[0];
    const float* w  = (const float*)d_in[1];
    const float* X  = (const float*)d_in[2];
    const float* t1 = (const float*)d_in[3];
    const float* t2 = (const float*)d_in[4];
    float* out = (float*)d_out;

    k_zero_cnt <<<16, 256>>>();
    k_hist     <<<EE/256, 256>>>(ei);
    k_escan    <<<1, 1024>>>();
    k_ebucket  <<<EE/256, 256>>>(ei, w);
    k_build_adj<<<NN, 256>>>();
    k_spgemm   <<<NN, 256>>>();
    k_stats    <<<1, 256>>>();
    k_sq       <<<NN, 256>>>(X);
    k_zbuild   <<<NN, 256>>>(X);
    k_edge     <<<EE/256, 256>>>(ei, w, t1, t2, out);
}